// round 2
// baseline (speedup 1.0000x reference)
#include <cuda_runtime.h>

#define NN 50000
#define NE 600000
#define HD 128
#define NG 128

// ---------------- scratch (static device globals; no allocations) ------------
__device__ float g_hA[NN * HD];   // ping: current node features
__device__ float g_hB[NN * HD];   // pong: m = h @ Wg
__device__ float g_deg[NN];
__device__ float g_dinv[NN];
__device__ float g_norm[NE];

// ---------------- prep: deg := 1 (self loop), out := 0 ----------------------
__global__ void k_prep(float* __restrict__ out) {
    int i = blockIdx.x * blockDim.x + threadIdx.x;
    if (i < NN) g_deg[i] = 1.0f;
    if (i < NG) out[i] = 0.0f;
}

__global__ void k_deg(const int* __restrict__ ei) {
    int e = blockIdx.x * blockDim.x + threadIdx.x;
    if (e < NE) atomicAdd(&g_deg[ei[NE + e]], 1.0f);
}

__global__ void k_dinv() {
    int i = blockIdx.x * blockDim.x + threadIdx.x;
    if (i < NN) g_dinv[i] = rsqrtf(g_deg[i]);
}

__global__ void k_enorm(const int* __restrict__ ei) {
    int e = blockIdx.x * blockDim.x + threadIdx.x;
    if (e < NE) g_norm[e] = g_dinv[ei[e]] * g_dinv[ei[NE + e]];
}

// ---------------- input MLP: g_hA = relu(x@W1 + b1) @ W2 + b2 ---------------
// Tile: 64 nodes x 128 cols per block of 256 threads; thread = 8 nodes x 4 cols.
__global__ __launch_bounds__(256) void k_gemm_in(
    const float* __restrict__ x,
    const float* __restrict__ W1, const float* __restrict__ b1,
    const float* __restrict__ W2, const float* __restrict__ b2)
{
    __shared__ float sA[64][32];
    __shared__ float sB[32][HD];
    __shared__ float sx[64];
    __shared__ float sW1[32], sb1[32];

    int tid = threadIdx.x;
    int tx = tid & 31;        // col group (4 cols)
    int ty = tid >> 5;        // node group (8 nodes)
    int nb = blockIdx.x * 64;

    if (tid < 64) { int gn = nb + tid; sx[tid] = (gn < NN) ? x[gn] : 0.0f; }

    float acc[8][4];
#pragma unroll
    for (int i = 0; i < 8; i++)
#pragma unroll
        for (int c = 0; c < 4; c++) acc[i][c] = 0.0f;

    for (int kc = 0; kc < 4; kc++) {
        __syncthreads();
        if (tid < 32) { sW1[tid] = W1[kc * 32 + tid]; sb1[tid] = b1[kc * 32 + tid]; }
        const float4* B4 = (const float4*)(W2 + kc * 32 * HD);
#pragma unroll
        for (int i = 0; i < 4; i++) ((float4*)sB)[tid + i * 256] = B4[tid + i * 256];
        __syncthreads();
#pragma unroll
        for (int i = 0; i < 8; i++) {
            int idx = tid + i * 256;
            int r = idx >> 5, k = idx & 31;
            sA[r][k] = fmaxf(fmaf(sx[r], sW1[k], sb1[k]), 0.0f);
        }
        __syncthreads();
#pragma unroll
        for (int kk = 0; kk < 32; kk += 4) {
            float4 bb0 = *(const float4*)&sB[kk + 0][tx * 4];
            float4 bb1 = *(const float4*)&sB[kk + 1][tx * 4];
            float4 bb2 = *(const float4*)&sB[kk + 2][tx * 4];
            float4 bb3 = *(const float4*)&sB[kk + 3][tx * 4];
#pragma unroll
            for (int i = 0; i < 8; i++) {
                float4 a = *(const float4*)&sA[ty * 8 + i][kk];
                acc[i][0] = fmaf(a.x, bb0.x, acc[i][0]); acc[i][1] = fmaf(a.x, bb0.y, acc[i][1]);
                acc[i][2] = fmaf(a.x, bb0.z, acc[i][2]); acc[i][3] = fmaf(a.x, bb0.w, acc[i][3]);
                acc[i][0] = fmaf(a.y, bb1.x, acc[i][0]); acc[i][1] = fmaf(a.y, bb1.y, acc[i][1]);
                acc[i][2] = fmaf(a.y, bb1.z, acc[i][2]); acc[i][3] = fmaf(a.y, bb1.w, acc[i][3]);
                acc[i][0] = fmaf(a.z, bb2.x, acc[i][0]); acc[i][1] = fmaf(a.z, bb2.y, acc[i][1]);
                acc[i][2] = fmaf(a.z, bb2.z, acc[i][2]); acc[i][3] = fmaf(a.z, bb2.w, acc[i][3]);
                acc[i][0] = fmaf(a.w, bb3.x, acc[i][0]); acc[i][1] = fmaf(a.w, bb3.y, acc[i][1]);
                acc[i][2] = fmaf(a.w, bb3.z, acc[i][2]); acc[i][3] = fmaf(a.w, bb3.w, acc[i][3]);
            }
        }
    }
    float4 bias = ((const float4*)b2)[tx];
#pragma unroll
    for (int i = 0; i < 8; i++) {
        int gn = nb + ty * 8 + i;
        if (gn < NN) {
            float4 v = make_float4(acc[i][0] + bias.x, acc[i][1] + bias.y,
                                   acc[i][2] + bias.z, acc[i][3] + bias.w);
            *((float4*)(g_hA + gn * HD + tx * 4)) = v;
        }
    }
}

// ---------------- layer GEMM: g_hB = op(g_hA) @ B  (op = optional relu) -----
template <bool RELU>
__global__ __launch_bounds__(256) void k_gemm(const float* __restrict__ B)
{
    __shared__ float sA[64][32];
    __shared__ float sB[32][HD];

    int tid = threadIdx.x;
    int tx = tid & 31;
    int ty = tid >> 5;
    int nb = blockIdx.x * 64;

    float acc[8][4];
#pragma unroll
    for (int i = 0; i < 8; i++)
#pragma unroll
        for (int c = 0; c < 4; c++) acc[i][c] = 0.0f;

    for (int kc = 0; kc < 4; kc++) {
        if (kc) __syncthreads();
#pragma unroll
        for (int i = 0; i < 2; i++) {
            int idx = tid + i * 256;
            int r = idx >> 3, c = idx & 7;
            int gn = nb + r;
            float4 v = make_float4(0.f, 0.f, 0.f, 0.f);
            if (gn < NN) v = ((const float4*)(g_hA + gn * HD + kc * 32))[c];
            if (RELU) {
                v.x = fmaxf(v.x, 0.f); v.y = fmaxf(v.y, 0.f);
                v.z = fmaxf(v.z, 0.f); v.w = fmaxf(v.w, 0.f);
            }
            *((float4*)&sA[r][c * 4]) = v;
        }
        const float4* B4 = (const float4*)(B + kc * 32 * HD);
#pragma unroll
        for (int i = 0; i < 4; i++) ((float4*)sB)[tid + i * 256] = B4[tid + i * 256];
        __syncthreads();
#pragma unroll
        for (int kk = 0; kk < 32; kk += 4) {
            float4 bb0 = *(const float4*)&sB[kk + 0][tx * 4];
            float4 bb1 = *(const float4*)&sB[kk + 1][tx * 4];
            float4 bb2 = *(const float4*)&sB[kk + 2][tx * 4];
            float4 bb3 = *(const float4*)&sB[kk + 3][tx * 4];
#pragma unroll
            for (int i = 0; i < 8; i++) {
                float4 a = *(const float4*)&sA[ty * 8 + i][kk];
                acc[i][0] = fmaf(a.x, bb0.x, acc[i][0]); acc[i][1] = fmaf(a.x, bb0.y, acc[i][1]);
                acc[i][2] = fmaf(a.x, bb0.z, acc[i][2]); acc[i][3] = fmaf(a.x, bb0.w, acc[i][3]);
                acc[i][0] = fmaf(a.y, bb1.x, acc[i][0]); acc[i][1] = fmaf(a.y, bb1.y, acc[i][1]);
                acc[i][2] = fmaf(a.y, bb1.z, acc[i][2]); acc[i][3] = fmaf(a.y, bb1.w, acc[i][3]);
                acc[i][0] = fmaf(a.z, bb2.x, acc[i][0]); acc[i][1] = fmaf(a.z, bb2.y, acc[i][1]);
                acc[i][2] = fmaf(a.z, bb2.z, acc[i][2]); acc[i][3] = fmaf(a.z, bb2.w, acc[i][3]);
                acc[i][0] = fmaf(a.w, bb3.x, acc[i][0]); acc[i][1] = fmaf(a.w, bb3.y, acc[i][1]);
                acc[i][2] = fmaf(a.w, bb3.z, acc[i][2]); acc[i][3] = fmaf(a.w, bb3.w, acc[i][3]);
            }
        }
    }
#pragma unroll
    for (int i = 0; i < 8; i++) {
        int gn = nb + ty * 8 + i;
        if (gn < NN) {
            float4 v = make_float4(acc[i][0], acc[i][1], acc[i][2], acc[i][3]);
            *((float4*)(g_hB + gn * HD + tx * 4)) = v;
        }
    }
}

// ----- aggregation init: g_hA[n] = g_hB[n] * dinv[n]^2 + bg  (self-loop + bias)
__global__ void k_agg_init(const float* __restrict__ bg) {
    int t = blockIdx.x * blockDim.x + threadIdx.x;
    if (t >= NN * 32) return;
    int n = t >> 5, c = t & 31;
    float d = g_dinv[n];
    float s = d * d;
    float4 m = ((const float4*)g_hB)[t];
    float4 bv = ((const float4*)bg)[c];
    float4 r;
    r.x = fmaf(m.x, s, bv.x); r.y = fmaf(m.y, s, bv.y);
    r.z = fmaf(m.z, s, bv.z); r.w = fmaf(m.w, s, bv.w);
    ((float4*)g_hA)[t] = r;
}

// ----- edge scatter: g_hA[col] += g_hB[row] * norm[e]  (float4 vector RED) ---
__global__ void k_scatter(const int* __restrict__ ei) {
    int t = blockIdx.x * blockDim.x + threadIdx.x;
    if (t >= NE * 32) return;
    int e = t >> 5, c = t & 31;
    int r  = ei[e];
    int cl = ei[NE + e];
    float nm = g_norm[e];
    float4 v = ((const float4*)g_hB)[r * 32 + c];
    v.x *= nm; v.y *= nm; v.z *= nm; v.w *= nm;
    atomicAdd(((float4*)g_hA) + cl * 32 + c, v);
}

// ----- output MLP + readout: out[g] += relu(relu(h)@W3+b3)@W4 + b4 ----------
__global__ __launch_bounds__(256) void k_final(
    const float* __restrict__ W3, const float* __restrict__ b3,
    const float* __restrict__ W4, const float* __restrict__ b4,
    const int* __restrict__ batch, float* __restrict__ out)
{
    __shared__ float sW3[HD * 64];
    __shared__ float sb3[64], sW4[64];
    __shared__ float sh[8][HD];

    int tid = threadIdx.x;
    for (int i = tid; i < HD * 64; i += 256) sW3[i] = W3[i];
    if (tid < 64) { sb3[tid] = b3[tid]; sW4[tid] = W4[tid]; }
    __syncthreads();

    float b4v = b4[0];
    int warp = tid >> 5, lane = tid & 31;

    for (int n = blockIdx.x * 8 + warp; n < NN; n += gridDim.x * 8) {
        float4 hv = ((const float4*)(g_hA + n * HD))[lane];
        hv.x = fmaxf(hv.x, 0.f); hv.y = fmaxf(hv.y, 0.f);
        hv.z = fmaxf(hv.z, 0.f); hv.w = fmaxf(hv.w, 0.f);
        ((float4*)sh[warp])[lane] = hv;
        __syncwarp();

        float a0 = sb3[lane], a1 = sb3[lane + 32];
#pragma unroll 8
        for (int j = 0; j < HD; j++) {
            float hj = sh[warp][j];
            a0 = fmaf(hj, sW3[j * 64 + lane], a0);
            a1 = fmaf(hj, sW3[j * 64 + lane + 32], a1);
        }
        a0 = fmaxf(a0, 0.f); a1 = fmaxf(a1, 0.f);
        float y = fmaf(a0, sW4[lane], a1 * sW4[lane + 32]);
#pragma unroll
        for (int off = 16; off; off >>= 1) y += __shfl_down_sync(0xFFFFFFFFu, y, off);
        if (lane == 0) atomicAdd(&out[batch[n]], y + b4v);
        __syncwarp();
    }
}

// ---------------------------------------------------------------------------
extern "C" void kernel_launch(void* const* d_in, const int* in_sizes, int n_in,
                              void* d_out, int out_size)
{
    const float* x     = (const float*)d_in[0];
    // d_in[1] = pos (unused by the reference network)
    const int*   ei    = (const int*)d_in[2];
    const int*   batch = (const int*)d_in[3];
    const float* W1 = (const float*)d_in[4];
    const float* b1 = (const float*)d_in[5];
    const float* W2 = (const float*)d_in[6];
    const float* b2 = (const float*)d_in[7];
    const float* Wg = (const float*)d_in[8];
    const float* bg = (const float*)d_in[9];
    const float* W3 = (const float*)d_in[10];
    const float* b3 = (const float*)d_in[11];
    const float* W4 = (const float*)d_in[12];
    const float* b4 = (const float*)d_in[13];
    float* out = (float*)d_out;

    k_prep<<<(NN + 255) / 256, 256>>>(out);
    k_deg<<<(NE + 255) / 256, 256>>>(ei);
    k_dinv<<<(NN + 255) / 256, 256>>>();
    k_enorm<<<(NE + 255) / 256, 256>>>(ei);

    k_gemm_in<<<(NN + 63) / 64, 256>>>(x, W1, b1, W2, b2);

    for (int l = 0; l < 3; l++) {
        if (l == 0) k_gemm<false><<<(NN + 63) / 64, 256>>>(Wg + l * HD * HD);
        else        k_gemm<true ><<<(NN + 63) / 64, 256>>>(Wg + l * HD * HD);
        k_agg_init<<<(NN * 32 + 255) / 256, 256>>>(bg + l * HD);
        k_scatter<<<(NE * 32 + 255) / 256, 256>>>(ei);
    }

    k_final<<<592, 256>>>(W3, b3, W4, b4, batch, out);
}

// round 5
// speedup vs baseline: 1.4685x; 1.4685x over previous
#include <cuda_runtime.h>

#define NN 50000
#define NE 600000
#define HD 128
#define NG 128
#define SCAN_B 1024
#define NSCANB ((NN + SCAN_B - 1) / SCAN_B)   // 49

// ---------------- scratch (static device globals; no allocations) ------------
__device__ float g_hA[NN * HD];     // current node features (relu'd layer output)
__device__ float g_hB[NN * HD];     // m * dinv[row]
__device__ float g_dinv[NN];
__device__ int   g_degi[NN];        // incoming edge count (no self loop)
__device__ int   g_scan[NN];
__device__ int   g_bsum[NSCANB];
__device__ int   g_boff[NSCANB];
__device__ int   g_rowstart[NN];
__device__ int   g_cursor[NN];
__device__ int   g_csrc[NE];        // CSR (by dest): source node ids

// ---------------- prep ------------------------------------------------------
__global__ void k_prep(float* __restrict__ out) {
    int i = blockIdx.x * blockDim.x + threadIdx.x;
    if (i < NN) g_degi[i] = 0;
    if (i < NG) out[i] = 0.0f;
}

__global__ void k_deg(const int* __restrict__ ei) {
    int e = blockIdx.x * blockDim.x + threadIdx.x;
    if (e < NE) atomicAdd(&g_degi[ei[NE + e]], 1);
}

__global__ void k_dinv() {
    int i = blockIdx.x * blockDim.x + threadIdx.x;
    if (i < NN) g_dinv[i] = rsqrtf((float)g_degi[i] + 1.0f);
}

// ---------------- scan (exclusive prefix over g_degi) -----------------------
__global__ __launch_bounds__(SCAN_B) void k_scan1() {
    __shared__ int sd[SCAN_B];
    int tid = threadIdx.x;
    int idx = blockIdx.x * SCAN_B + tid;
    int v = (idx < NN) ? g_degi[idx] : 0;
    sd[tid] = v;
    __syncthreads();
    for (int off = 1; off < SCAN_B; off <<= 1) {
        int t = (tid >= off) ? sd[tid - off] : 0;
        __syncthreads();
        sd[tid] += t;
        __syncthreads();
    }
    if (idx < NN) g_scan[idx] = sd[tid];
    if (tid == SCAN_B - 1) g_bsum[blockIdx.x] = sd[tid];
}

__global__ void k_scan2() {
    if (threadIdx.x == 0) {
        int a = 0;
        for (int b = 0; b < NSCANB; b++) { g_boff[b] = a; a += g_bsum[b]; }
    }
}

__global__ void k_scan3() {
    int i = blockIdx.x * blockDim.x + threadIdx.x;
    if (i < NN) {
        int rs = g_scan[i] - g_degi[i] + g_boff[i >> 10];
        g_rowstart[i] = rs;
        g_cursor[i] = rs;
    }
}

__global__ void k_fill(const int* __restrict__ ei) {
    int e = blockIdx.x * blockDim.x + threadIdx.x;
    if (e < NE) {
        int r = ei[e], c = ei[NE + e];
        int slot = atomicAdd(&g_cursor[c], 1);
        g_csrc[slot] = r;
    }
}

// ---------------- input MLP: g_hA = relu(x@W1 + b1) @ W2 + b2 ---------------
__global__ __launch_bounds__(256) void k_gemm_in(
    const float* __restrict__ x,
    const float* __restrict__ W1, const float* __restrict__ b1,
    const float* __restrict__ W2, const float* __restrict__ b2)
{
    __shared__ float sA[64][32];
    __shared__ float sB[32][HD];
    __shared__ float sx[64];
    __shared__ float sW1[32], sb1[32];

    int tid = threadIdx.x;
    int tx = tid & 31;
    int ty = tid >> 5;
    int nb = blockIdx.x * 64;

    if (tid < 64) { int gn = nb + tid; sx[tid] = (gn < NN) ? x[gn] : 0.0f; }

    float acc[8][4];
#pragma unroll
    for (int i = 0; i < 8; i++)
#pragma unroll
        for (int c = 0; c < 4; c++) acc[i][c] = 0.0f;

    for (int kc = 0; kc < 4; kc++) {
        __syncthreads();
        if (tid < 32) { sW1[tid] = W1[kc * 32 + tid]; sb1[tid] = b1[kc * 32 + tid]; }
        const float4* B4 = (const float4*)(W2 + kc * 32 * HD);
#pragma unroll
        for (int i = 0; i < 4; i++) ((float4*)sB)[tid + i * 256] = B4[tid + i * 256];
        __syncthreads();
#pragma unroll
        for (int i = 0; i < 8; i++) {
            int idx = tid + i * 256;
            int r = idx >> 5, k = idx & 31;
            sA[r][k] = fmaxf(fmaf(sx[r], sW1[k], sb1[k]), 0.0f);
        }
        __syncthreads();
#pragma unroll
        for (int kk = 0; kk < 32; kk += 4) {
            float4 bb0 = *(const float4*)&sB[kk + 0][tx * 4];
            float4 bb1 = *(const float4*)&sB[kk + 1][tx * 4];
            float4 bb2 = *(const float4*)&sB[kk + 2][tx * 4];
            float4 bb3 = *(const float4*)&sB[kk + 3][tx * 4];
#pragma unroll
            for (int i = 0; i < 8; i++) {
                float4 a = *(const float4*)&sA[ty * 8 + i][kk];
                acc[i][0] = fmaf(a.x, bb0.x, acc[i][0]); acc[i][1] = fmaf(a.x, bb0.y, acc[i][1]);
                acc[i][2] = fmaf(a.x, bb0.z, acc[i][2]); acc[i][3] = fmaf(a.x, bb0.w, acc[i][3]);
                acc[i][0] = fmaf(a.y, bb1.x, acc[i][0]); acc[i][1] = fmaf(a.y, bb1.y, acc[i][1]);
                acc[i][2] = fmaf(a.y, bb1.z, acc[i][2]); acc[i][3] = fmaf(a.y, bb1.w, acc[i][3]);
                acc[i][0] = fmaf(a.z, bb2.x, acc[i][0]); acc[i][1] = fmaf(a.z, bb2.y, acc[i][1]);
                acc[i][2] = fmaf(a.z, bb2.z, acc[i][2]); acc[i][3] = fmaf(a.z, bb2.w, acc[i][3]);
                acc[i][0] = fmaf(a.w, bb3.x, acc[i][0]); acc[i][1] = fmaf(a.w, bb3.y, acc[i][1]);
                acc[i][2] = fmaf(a.w, bb3.z, acc[i][2]); acc[i][3] = fmaf(a.w, bb3.w, acc[i][3]);
            }
        }
    }
    float4 bias = ((const float4*)b2)[tx];
#pragma unroll
    for (int i = 0; i < 8; i++) {
        int gn = nb + ty * 8 + i;
        if (gn < NN) {
            float4 v = make_float4(acc[i][0] + bias.x, acc[i][1] + bias.y,
                                   acc[i][2] + bias.z, acc[i][3] + bias.w);
            *((float4*)(g_hA + gn * HD + tx * 4)) = v;
        }
    }
}

// ------- layer GEMM: g_hB[n] = (g_hA[n] @ Wg) * dinv[n]  (epilogue-fused) ---
__global__ __launch_bounds__(256) void k_gemm(const float* __restrict__ B)
{
    __shared__ float sA[64][32];
    __shared__ float sB[32][HD];

    int tid = threadIdx.x;
    int tx = tid & 31;
    int ty = tid >> 5;
    int nb = blockIdx.x * 64;

    float acc[8][4];
#pragma unroll
    for (int i = 0; i < 8; i++)
#pragma unroll
        for (int c = 0; c < 4; c++) acc[i][c] = 0.0f;

    for (int kc = 0; kc < 4; kc++) {
        if (kc) __syncthreads();
#pragma unroll
        for (int i = 0; i < 2; i++) {
            int idx = tid + i * 256;
            int r = idx >> 3, c = idx & 7;
            int gn = nb + r;
            float4 v = make_float4(0.f, 0.f, 0.f, 0.f);
            if (gn < NN) v = ((const float4*)(g_hA + gn * HD + kc * 32))[c];
            *((float4*)&sA[r][c * 4]) = v;
        }
        const float4* B4 = (const float4*)(B + kc * 32 * HD);
#pragma unroll
        for (int i = 0; i < 4; i++) ((float4*)sB)[tid + i * 256] = B4[tid + i * 256];
        __syncthreads();
#pragma unroll
        for (int kk = 0; kk < 32; kk += 4) {
            float4 bb0 = *(const float4*)&sB[kk + 0][tx * 4];
            float4 bb1 = *(const float4*)&sB[kk + 1][tx * 4];
            float4 bb2 = *(const float4*)&sB[kk + 2][tx * 4];
            float4 bb3 = *(const float4*)&sB[kk + 3][tx * 4];
#pragma unroll
            for (int i = 0; i < 8; i++) {
                float4 a = *(const float4*)&sA[ty * 8 + i][kk];
                acc[i][0] = fmaf(a.x, bb0.x, acc[i][0]); acc[i][1] = fmaf(a.x, bb0.y, acc[i][1]);
                acc[i][2] = fmaf(a.x, bb0.z, acc[i][2]); acc[i][3] = fmaf(a.x, bb0.w, acc[i][3]);
                acc[i][0] = fmaf(a.y, bb1.x, acc[i][0]); acc[i][1] = fmaf(a.y, bb1.y, acc[i][1]);
                acc[i][2] = fmaf(a.y, bb1.z, acc[i][2]); acc[i][3] = fmaf(a.y, bb1.w, acc[i][3]);
                acc[i][0] = fmaf(a.z, bb2.x, acc[i][0]); acc[i][1] = fmaf(a.z, bb2.y, acc[i][1]);
                acc[i][2] = fmaf(a.z, bb2.z, acc[i][2]); acc[i][3] = fmaf(a.z, bb2.w, acc[i][3]);
                acc[i][0] = fmaf(a.w, bb3.x, acc[i][0]); acc[i][1] = fmaf(a.w, bb3.y, acc[i][1]);
                acc[i][2] = fmaf(a.w, bb3.z, acc[i][2]); acc[i][3] = fmaf(a.w, bb3.w, acc[i][3]);
            }
        }
    }
#pragma unroll
    for (int i = 0; i < 8; i++) {
        int gn = nb + ty * 8 + i;
        if (gn < NN) {
            float d = g_dinv[gn];
            float4 v = make_float4(acc[i][0] * d, acc[i][1] * d, acc[i][2] * d, acc[i][3] * d);
            *((float4*)(g_hB + gn * HD + tx * 4)) = v;
        }
    }
}

// ----- aggregation (CSR gather): g_hA[n] = relu(dinv[n]*(self + Σ src) + bg)
__global__ __launch_bounds__(256) void k_agg(const float* __restrict__ bg) {
    int w = (blockIdx.x * blockDim.x + threadIdx.x) >> 5;
    int lane = threadIdx.x & 31;
    if (w >= NN) return;
    int s = g_rowstart[w];
    int e = s + g_degi[w];

    float4 acc = ((const float4*)g_hB)[w * 32 + lane];   // self term
    int i = s;
    for (; i + 1 < e; i += 2) {
        int s0 = g_csrc[i], s1 = g_csrc[i + 1];
        float4 v0 = ((const float4*)g_hB)[s0 * 32 + lane];
        float4 v1 = ((const float4*)g_hB)[s1 * 32 + lane];
        acc.x += v0.x + v1.x; acc.y += v0.y + v1.y;
        acc.z += v0.z + v1.z; acc.w += v0.w + v1.w;
    }
    if (i < e) {
        float4 v0 = ((const float4*)g_hB)[g_csrc[i] * 32 + lane];
        acc.x += v0.x; acc.y += v0.y; acc.z += v0.z; acc.w += v0.w;
    }
    float d = g_dinv[w];
    float4 bv = ((const float4*)bg)[lane];
    float4 r;
    r.x = fmaxf(fmaf(acc.x, d, bv.x), 0.f);
    r.y = fmaxf(fmaf(acc.y, d, bv.y), 0.f);
    r.z = fmaxf(fmaf(acc.z, d, bv.z), 0.f);
    r.w = fmaxf(fmaf(acc.w, d, bv.w), 0.f);
    ((float4*)g_hA)[w * 32 + lane] = r;
}

// ----- output MLP + readout (tiled GEMM + GEMV + shfl reduce + atomic) ------
// 64 nodes x 64 cols per block; 256 threads; thread = 4 nodes x 4 cols.
__global__ __launch_bounds__(256) void k_final(
    const float* __restrict__ W3, const float* __restrict__ b3,
    const float* __restrict__ W4, const float* __restrict__ b4,
    const int* __restrict__ batch, float* __restrict__ out)
{
    __shared__ float sA[64][32];
    __shared__ float sB[32][64];
    __shared__ float sW4[64];

    int tid = threadIdx.x;
    int tx = tid & 15;       // col group (4 cols of 64)
    int ty = tid >> 4;       // node group (4 nodes of 64)
    int nb = blockIdx.x * 64;

    if (tid < 64) sW4[tid] = W4[tid];

    float acc[4][4];
#pragma unroll
    for (int i = 0; i < 4; i++)
#pragma unroll
        for (int j = 0; j < 4; j++) acc[i][j] = 0.0f;

    for (int kc = 0; kc < 4; kc++) {
        if (kc) __syncthreads();
        // load A tile: 64 nodes x 32 k  (512 float4, 2 per thread)
#pragma unroll
        for (int i = 0; i < 2; i++) {
            int idx = tid + i * 256;
            int r = idx >> 3, c = idx & 7;
            int gn = nb + r;
            float4 v = make_float4(0.f, 0.f, 0.f, 0.f);
            if (gn < NN) v = ((const float4*)(g_hA + gn * HD + kc * 32))[c];
            *((float4*)&sA[r][c * 4]) = v;
        }
        // load B tile: W3 rows kc*32..+31, 64 cols (512 float4, 2 per thread)
        const float4* B4 = (const float4*)(W3 + kc * 32 * 64);
#pragma unroll
        for (int i = 0; i < 2; i++) ((float4*)sB)[tid + i * 256] = B4[tid + i * 256];
        __syncthreads();
#pragma unroll
        for (int kk = 0; kk < 32; kk += 4) {
            float4 bb0 = *(const float4*)&sB[kk + 0][tx * 4];
            float4 bb1 = *(const float4*)&sB[kk + 1][tx * 4];
            float4 bb2 = *(const float4*)&sB[kk + 2][tx * 4];
            float4 bb3 = *(const float4*)&sB[kk + 3][tx * 4];
#pragma unroll
            for (int i = 0; i < 4; i++) {
                float4 a = *(const float4*)&sA[ty * 4 + i][kk];
                acc[i][0] = fmaf(a.x, bb0.x, acc[i][0]); acc[i][1] = fmaf(a.x, bb0.y, acc[i][1]);
                acc[i][2] = fmaf(a.x, bb0.z, acc[i][2]); acc[i][3] = fmaf(a.x, bb0.w, acc[i][3]);
                acc[i][0] = fmaf(a.y, bb1.x, acc[i][0]); acc[i][1] = fmaf(a.y, bb1.y, acc[i][1]);
                acc[i][2] = fmaf(a.y, bb1.z, acc[i][2]); acc[i][3] = fmaf(a.y, bb1.w, acc[i][3]);
                acc[i][0] = fmaf(a.z, bb2.x, acc[i][0]); acc[i][1] = fmaf(a.z, bb2.y, acc[i][1]);
                acc[i][2] = fmaf(a.z, bb2.z, acc[i][2]); acc[i][3] = fmaf(a.z, bb2.w, acc[i][3]);
                acc[i][0] = fmaf(a.w, bb3.x, acc[i][0]); acc[i][1] = fmaf(a.w, bb3.y, acc[i][1]);
                acc[i][2] = fmaf(a.w, bb3.z, acc[i][2]); acc[i][3] = fmaf(a.w, bb3.w, acc[i][3]);
            }
        }
    }

    // stage 2: t = relu(acc + b3), partial[i] = sum_j t[i][j]*W4[col]
    float4 b3v = ((const float4*)b3)[tx];
    float w40 = sW4[tx * 4 + 0], w41 = sW4[tx * 4 + 1];
    float w42 = sW4[tx * 4 + 2], w43 = sW4[tx * 4 + 3];
    float b4v = b4[0];

#pragma unroll
    for (int i = 0; i < 4; i++) {
        float t0 = fmaxf(acc[i][0] + b3v.x, 0.f);
        float t1 = fmaxf(acc[i][1] + b3v.y, 0.f);
        float t2 = fmaxf(acc[i][2] + b3v.z, 0.f);
        float t3 = fmaxf(acc[i][3] + b3v.w, 0.f);
        float p = fmaf(t0, w40, fmaf(t1, w41, fmaf(t2, w42, t3 * w43)));
        // reduce across the 16 tx-threads (contiguous lanes within half-warp)
#pragma unroll
        for (int off = 8; off; off >>= 1) p += __shfl_xor_sync(0xFFFFFFFFu, p, off);
        if (tx == 0) {
            int gn = nb + ty * 4 + i;
            if (gn < NN) atomicAdd(&out[batch[gn]], p + b4v);
        }
    }
}

// ---------------------------------------------------------------------------
extern "C" void kernel_launch(void* const* d_in, const int* in_sizes, int n_in,
                              void* d_out, int out_size)
{
    const float* x     = (const float*)d_in[0];
    const int*   ei    = (const int*)d_in[2];
    const int*   batch = (const int*)d_in[3];
    const float* W1 = (const float*)d_in[4];
    const float* b1 = (const float*)d_in[5];
    const float* W2 = (const float*)d_in[6];
    const float* b2 = (const float*)d_in[7];
    const float* Wg = (const float*)d_in[8];
    const float* bg = (const float*)d_in[9];
    const float* W3 = (const float*)d_in[10];
    const float* b3 = (const float*)d_in[11];
    const float* W4 = (const float*)d_in[12];
    const float* b4 = (const float*)d_in[13];
    float* out = (float*)d_out;

    k_prep<<<(NN + 255) / 256, 256>>>(out);
    k_deg<<<(NE + 255) / 256, 256>>>(ei);
    k_dinv<<<(NN + 255) / 256, 256>>>();
    k_scan1<<<NSCANB, SCAN_B>>>();
    k_scan2<<<1, 32>>>();
    k_scan3<<<(NN + 255) / 256, 256>>>();
    k_fill<<<(NE + 255) / 256, 256>>>(ei);

    k_gemm_in<<<(NN + 63) / 64, 256>>>(x, W1, b1, W2, b2);

    for (int l = 0; l < 3; l++) {
        k_gemm<<<(NN + 63) / 64, 256>>>(Wg + l * HD * HD);
        k_agg<<<(NN * 32 + 255) / 256, 256>>>(bg + l * HD);
    }

    k_final<<<(NN + 63) / 64, 256>>>(W3, b3, W4, b4, batch, out);
}